// round 17
// baseline (speedup 1.0000x reference)
#include <cuda_runtime.h>
#include <cuda_bf16.h>
#include <cstdint>

#define N_TOK 16384
#define D 512
#define K 8192

typedef unsigned int u32;
typedef unsigned short u16;
typedef unsigned long long u64;

constexpr float DECAYC = 0.99f;
constexpr float OMD = (float)(1.0 - 0.99);
constexpr float EPSC = 1e-5f;
constexpr float MARGIN = 0.5f;
#define CAP 32

// output layout (concatenated, float32)
#define OFF_Q    0
#define OFF_LOSS 8388608
#define OFF_IDX  8388609
#define OFF_CS   8404993
#define OFF_EMAW 8413185
#define OFF_W    12607489

// device scratch
__device__ float g_cbnorm[K];
__device__ float g_counts[K];
__device__ float g_cs_pre[K];
__device__ float g_loss;
__device__ float g_sum;
// chunk-major, pre-swizzled normalized codebook in e4m3:
// chunk g (0..127): tile = g>>2 (256 codes), dblock = g&3 (128 dims)
// byte (row 0..255, unit j 0..7 of 16B) at g*32768 + row*128 + ((j^(row&7))*16)
__device__ unsigned char g_wb[K * D];
__device__ int g_ccnt[N_TOK];
__device__ int g_cand[N_TOK * CAP];

__device__ __forceinline__ u64 packkey(float v, int k) {
    u32 b = __float_as_uint(v);
    b = (b & 0x80000000u) ? ~b : (b | 0x80000000u);
    return ((u64)b << 32) | (u32)k;
}
__device__ __forceinline__ float unpackval(u64 key) {
    u32 b = (u32)(key >> 32);
    b = (b & 0x80000000u) ? (b & 0x7FFFFFFFu) : ~b;
    return __uint_as_float(b);
}
// pack 4 floats -> 4 e4m3 bytes (memory order v0,v1,v2,v3)
// cvt.rn.satfinite.e4m3x2.f32 d, a, b packs {b (lo byte), a (hi byte)} into .b16
__device__ __forceinline__ u32 pack_e4m3x4(float v0, float v1, float v2, float v3) {
    u16 lo, hi;
    asm("cvt.rn.satfinite.e4m3x2.f32 %0, %1, %2;" : "=h"(lo) : "f"(v1), "f"(v0));
    asm("cvt.rn.satfinite.e4m3x2.f32 %0, %1, %2;" : "=h"(hi) : "f"(v3), "f"(v2));
    return (u32)lo | ((u32)hi << 16);
}

// ---------------------------------------------------------------------------
// mbarrier + bulk-copy helpers (sm_90 baseline PTX)
// ---------------------------------------------------------------------------
__device__ __forceinline__ void mbar_init(u32 addr, u32 count) {
    asm volatile("mbarrier.init.shared.b64 [%0], %1;" :: "r"(addr), "r"(count) : "memory");
}
__device__ __forceinline__ void mbar_expect(u32 addr, u32 bytes) {
    asm volatile("mbarrier.arrive.expect_tx.shared.b64 _, [%0], %1;"
                 :: "r"(addr), "r"(bytes) : "memory");
}
__device__ __forceinline__ void mbar_wait(u32 addr, u32 phase) {
    asm volatile(
        "{\n\t.reg .pred P;\n"
        "W_%=:\n\t"
        "mbarrier.try_wait.parity.acquire.cta.shared::cta.b64 P, [%0], %1, 0x989680;\n\t"
        "@P bra.uni D_%=;\n\t"
        "bra.uni W_%=;\n"
        "D_%=:\n\t}"
        :: "r"(addr), "r"(phase) : "memory");
}
__device__ __forceinline__ void bulk_g2s(u32 dst_smem, const void* src, u32 bytes, u32 mbar) {
    asm volatile(
        "cp.async.bulk.shared::cluster.global.mbarrier::complete_tx::bytes "
        "[%0], [%1], %2, [%3];"
        :: "r"(dst_smem), "l"(src), "r"(bytes), "r"(mbar) : "memory");
}

// ---------------------------------------------------------------------------
// k0 (merged): [0,1024) codebook norms + chunk-major pre-swizzled e4m3 write
//              + zero accum; [1024,5120) ema_w*DECAY
// ---------------------------------------------------------------------------
__global__ void __launch_bounds__(256) setup_kernel(const float* __restrict__ w,
                                                    const float* __restrict__ emaw,
                                                    float* __restrict__ out) {
    int bid = blockIdx.x;
    if (bid < 1024) {
        int gid  = bid * 256 + threadIdx.x;
        int wid  = gid >> 5;          // code row 0..8191
        int lane = threadIdx.x & 31;

        const float* row = w + (size_t)wid * D;
        float s = 0.f;
#pragma unroll
        for (int c = 0; c < 4; c++) {
            float4 v = *(const float4*)&row[lane * 4 + c * 128];
            s += v.x * v.x + v.y * v.y + v.z * v.z + v.w * v.w;
        }
#pragma unroll
        for (int o = 16; o; o >>= 1) s += __shfl_xor_sync(0xffffffffu, s, o);
        float cbn = rsqrtf(s + 1e-12f);
        if (lane == 0) g_cbnorm[wid] = cbn;

        // write normalized e4m3 into chunk-major pre-swizzled layout
        int tile = wid >> 8;          // 0..31
        int rin  = wid & 255;
        int u    = lane;              // 16B unit 0..31 (16 dims each)
        int db   = u >> 3;            // dblock 0..3
        int j    = u & 7;
        const float* src = &row[u * 16];
        float4 f0 = *(const float4*)(src + 0);
        float4 f1 = *(const float4*)(src + 4);
        float4 f2 = *(const float4*)(src + 8);
        float4 f3 = *(const float4*)(src + 12);
        uint4 pv;
        pv.x = pack_e4m3x4(f0.x * cbn, f0.y * cbn, f0.z * cbn, f0.w * cbn);
        pv.y = pack_e4m3x4(f1.x * cbn, f1.y * cbn, f1.z * cbn, f1.w * cbn);
        pv.z = pack_e4m3x4(f2.x * cbn, f2.y * cbn, f2.z * cbn, f2.w * cbn);
        pv.w = pack_e4m3x4(f3.x * cbn, f3.y * cbn, f3.z * cbn, f3.w * cbn);
        size_t goff = ((size_t)(tile * 4 + db) << 15)
                    + (size_t)(rin * 128 + ((j ^ (rin & 7)) * 16));
        *(uint4*)(g_wb + goff) = pv;

        if (gid < K) g_counts[gid] = 0.f;
        if (gid < N_TOK) g_ccnt[gid] = 0;
        if (gid == 0) { g_loss = 0.f; g_sum = 0.f; }
    } else {
        int gid = (bid - 1024) * 256 + threadIdx.x;
        float4 v = *(const float4*)&emaw[gid * 4];
        float* o = out + OFF_EMAW + (size_t)gid * 4;
        o[0] = v.x * DECAYC;
        o[1] = v.y * DECAYC;
        o[2] = v.z * DECAYC;
        o[3] = v.w * DECAYC;
    }
}

// ---------------------------------------------------------------------------
// k1: e4m3 mma.sync (m16n8k32) argmax GEMM + fused rescore/gather tail.
// 128 tokens/CTA, 512 threads (16 warps, 4M x 4N), warp tile 32x64.
// 128-d chunks (GTOT=128), single cp.async.bulk per 32KB chunk + mbarrier.
// Loop: mbar-wait -> sync -> collect(prev tile) -> issue bulk(g+2) -> compute.
// ---------------------------------------------------------------------------
#define BLK_T 128
#define NTHREADS 512
#define SM_BEST 0
#define SM_MBAR 1024
#define SM_A    2048
#define SM_B    (SM_A + 65536)                // 67584 (A: 128 rows x 512B fp8)
#define B_STAGE 32768
#define SMEM_BYTES (SM_B + 3 * B_STAGE)       // 165888
#define GTOT 128                               // 32 tiles * 4 chunks (128d each)

__device__ __forceinline__ void ldsm4(u32& r0, u32& r1, u32& r2, u32& r3, u32 addr) {
    asm volatile("ldmatrix.sync.aligned.m8n8.x4.shared.b16 {%0,%1,%2,%3}, [%4];\n"
                 : "=r"(r0), "=r"(r1), "=r"(r2), "=r"(r3) : "r"(addr));
}

__device__ __forceinline__ void mma_acc(float* d, const u32* a, u32 b0, u32 b1) {
    asm volatile(
        "mma.sync.aligned.m16n8k32.row.col.f32.e4m3.e4m3.f32 "
        "{%0,%1,%2,%3}, {%4,%5,%6,%7}, {%8,%9}, {%0,%1,%2,%3};\n"
        : "+f"(d[0]), "+f"(d[1]), "+f"(d[2]), "+f"(d[3])
        : "r"(a[0]), "r"(a[1]), "r"(a[2]), "r"(a[3]), "r"(b0), "r"(b1));
}
__device__ __forceinline__ void mma_zero(float* d, const u32* a, u32 b0, u32 b1) {
    float z = 0.f;
    asm volatile(
        "mma.sync.aligned.m16n8k32.row.col.f32.e4m3.e4m3.f32 "
        "{%0,%1,%2,%3}, {%4,%5,%6,%7}, {%8,%9}, {%10,%10,%10,%10};\n"
        : "=f"(d[0]), "=f"(d[1]), "=f"(d[2]), "=f"(d[3])
        : "r"(a[0]), "r"(a[1]), "r"(a[2]), "r"(a[3]), "r"(b0), "r"(b1), "f"(z));
}

// B stage offset for (code row 0..255, 16B unit j 0..7); full 128B row
__device__ __forceinline__ u32 b_off(int row, int j) {
    return (u32)(row * 128 + ((j ^ (row & 7)) * 16));
}

__global__ void __launch_bounds__(NTHREADS, 1) mma_argmax_kernel(
        const float* __restrict__ x,
        const float* __restrict__ w,
        float* __restrict__ out) {
    extern __shared__ char dsm[];
    u64* best = (u64*)(dsm + SM_BEST);

    int tid  = threadIdx.x;
    int warp = tid >> 5;
    int lane = tid & 31;
    int r    = lane >> 2;     // 0..7
    int tg   = lane & 3;      // 0..3
    int warpM = warp >> 2;    // 0..3
    int warpN = warp & 3;     // 0..3
    int t0   = blockIdx.x * BLK_T;

    u32 sbase = (u32)__cvta_generic_to_shared(dsm);
    u32 mb = sbase + SM_MBAR;

    if (tid < BLK_T) best[tid] = packkey(-3e38f, 0);
    if (tid == 0) {
        mbar_init(mb + 0, 1);
        mbar_init(mb + 8, 1);
        mbar_init(mb + 16, 1);
    }

    // ---- load A: 128 tokens x 512 d fp32 -> e4m3, swizzled (512B rows) ----
#pragma unroll
    for (int i = 0; i < 8; i++) {
        int f   = i * NTHREADS + tid;     // 0..4095 16B units (16 fp8 each)
        int row = f >> 5;
        int u   = f & 31;
        const float* src = &x[(size_t)(t0 + row) * D + u * 16];
        float4 f0 = *(const float4*)(src + 0);
        float4 f1 = *(const float4*)(src + 4);
        float4 f2 = *(const float4*)(src + 8);
        float4 f3 = *(const float4*)(src + 12);
        uint4 v;
        v.x = pack_e4m3x4(f0.x, f0.y, f0.z, f0.w);
        v.y = pack_e4m3x4(f1.x, f1.y, f1.z, f1.w);
        v.z = pack_e4m3x4(f2.x, f2.y, f2.z, f2.w);
        v.w = pack_e4m3x4(f3.x, f3.y, f3.z, f3.w);
        *(uint4*)(dsm + SM_A + row * 512 + ((u ^ (row & 7)) * 16)) = v;
    }
    __syncthreads();   // mbars initialized; A visible before any compute

    // ---- prime: bulk-issue chunks 0,1 ----
    if (tid == 0) {
#pragma unroll
        for (int pg = 0; pg < 2; pg++) {
            mbar_expect(mb + pg * 8, B_STAGE);
            bulk_g2s(sbase + SM_B + pg * B_STAGE, g_wb + ((size_t)pg << 15),
                     B_STAGE, mb + pg * 8);
        }
    }

    // ldmatrix lane components (identical mapping, fp8 k32 semantics)
    int a_rowl = (lane & 15);             // + warpM*32 + mi*16
    int a_jl   = (lane >> 4);             // + c*8 + s*2
    int b_rowl = warpN * 64 + (lane & 7) + ((lane & 16) ? 8 : 0);
    int b_jl   = ((lane >> 3) & 1);       // + s*2

    float acc[2][8][4];
#pragma unroll
    for (int mi = 0; mi < 2; mi++)
#pragma unroll
        for (int ni = 0; ni < 8; ni++)
#pragma unroll
            for (int e = 0; e < 4; e++) acc[mi][ni][e] = 0.f;

    u32 ph0 = 0, ph1 = 0, ph2 = 0;

    for (int g = 0; g < GTOT; g++) {
        int c = g & 3;                    // d-chunk within tile (128 d each)
        int st = g % 3;

        // wait chunk g's bulk copy
        if (st == 0) { mbar_wait(mb + 0, ph0); ph0 ^= 1; }
        else if (st == 1) { mbar_wait(mb + 8, ph1); ph1 ^= 1; }
        else { mbar_wait(mb + 16, ph2); ph2 ^= 1; }
        __syncthreads();   // all threads past compute g-1; publishes prev atomicMax

        // ---- deferred candidate collection for the PREVIOUS tile ----
        if (c == 0 && g > 0) {
            int pkt = ((g >> 2) - 1) * 256;
#pragma unroll
            for (int mi = 0; mi < 2; mi++) {
#pragma unroll
                for (int h = 0; h < 2; h++) {
                    int lt = warpM * 32 + mi * 16 + h * 8 + r;
                    float thr = unpackval(best[lt]) - MARGIN;
                    int token = t0 + lt;
#pragma unroll
                    for (int ni = 0; ni < 8; ni++) {
                        int k0 = pkt + warpN * 64 + ni * 8 + 2 * tg;
#pragma unroll
                        for (int e = 0; e < 2; e++) {
                            if (acc[mi][ni][h * 2 + e] >= thr) {
                                int pos = atomicAdd(&g_ccnt[token], 1);
                                if (pos < CAP) g_cand[token * CAP + pos] = k0 + e;
                            }
                        }
                    }
                }
            }
        }

        // ---- issue bulk for chunk g+2 into stage (g+2)%3 == (g-1)%3 ----
        if (tid == 0 && g + 2 < GTOT) {
            int ng = g + 2, nst = ng % 3;
            mbar_expect(mb + nst * 8, B_STAGE);
            bulk_g2s(sbase + SM_B + nst * B_STAGE, g_wb + ((size_t)ng << 15),
                     B_STAGE, mb + nst * 8);
        }

        // ---- compute chunk g (128 d = 4 s-steps of k32) from stage st ----
        u32 bstage = sbase + SM_B + st * B_STAGE;
#pragma unroll
        for (int s = 0; s < 4; s++) {
            int aj = c * 8 + s * 2 + a_jl;
            u32 af[2][4];
#pragma unroll
            for (int mi = 0; mi < 2; mi++) {
                int R = warpM * 32 + mi * 16 + a_rowl;
                u32 addr = sbase + SM_A + R * 512 + ((aj ^ (R & 7)) * 16);
                ldsm4(af[mi][0], af[mi][1], af[mi][2], af[mi][3], addr);
            }
            int bj = s * 2 + b_jl;
#pragma unroll
            for (int nn = 0; nn < 4; nn++) {
                u32 b0, b1, b2, b3;
                int row = b_rowl + nn * 16;
                ldsm4(b0, b1, b2, b3, bstage + b_off(row, bj));
                if (s == 0 && c == 0) {
#pragma unroll
                    for (int mi = 0; mi < 2; mi++) {
                        mma_zero(acc[mi][nn*2],     af[mi], b0, b1);
                        mma_zero(acc[mi][nn*2 + 1], af[mi], b2, b3);
                    }
                } else {
#pragma unroll
                    for (int mi = 0; mi < 2; mi++) {
                        mma_acc(acc[mi][nn*2],     af[mi], b0, b1);
                        mma_acc(acc[mi][nn*2 + 1], af[mi], b2, b3);
                    }
                }
            }
        }

        // ---- tile complete: fold running max, publish (barrier-free) ----
        if (c == 3) {
            int kt = (g >> 2) * 256;
#pragma unroll
            for (int mi = 0; mi < 2; mi++) {
#pragma unroll
                for (int h = 0; h < 2; h++) {
                    float bv = -3e38f; int bk = 0;
#pragma unroll
                    for (int ni = 0; ni < 8; ni++) {
                        int k0 = kt + warpN * 64 + ni * 8 + 2 * tg;
                        float v0 = acc[mi][ni][h * 2 + 0];
                        float v1 = acc[mi][ni][h * 2 + 1];
                        if (v0 > bv) { bv = v0; bk = k0; }
                        if (v1 > bv) { bv = v1; bk = k0 + 1; }
                    }
                    u64 key = packkey(bv, bk);
                    u64 o1 = __shfl_xor_sync(0xffffffffu, key, 1);
                    if (o1 > key) key = o1;
                    u64 o2 = __shfl_xor_sync(0xffffffffu, key, 2);
                    if (o2 > key) key = o2;
                    if (tg == 0)
                        atomicMax(&best[warpM * 32 + mi * 16 + h * 8 + r], key);
                }
            }
        }
    }

    // ---- final tile's collection (one more publish barrier) ----
    __syncthreads();
    {
        int pkt = (GTOT / 4 - 1) * 256;   // last tile's code base
#pragma unroll
        for (int mi = 0; mi < 2; mi++) {
#pragma unroll
            for (int h = 0; h < 2; h++) {
                int lt = warpM * 32 + mi * 16 + h * 8 + r;
                float thr = unpackval(best[lt]) - MARGIN;
                int token = t0 + lt;
#pragma unroll
                for (int ni = 0; ni < 8; ni++) {
                    int k0 = pkt + warpN * 64 + ni * 8 + 2 * tg;
#pragma unroll
                    for (int e = 0; e < 2; e++) {
                        if (acc[mi][ni][h * 2 + e] >= thr) {
                            int pos = atomicAdd(&g_ccnt[token], 1);
                            if (pos < CAP) g_cand[token * CAP + pos] = k0 + e;
                        }
                    }
                }
            }
        }
    }

    // =======================================================================
    // fused tail: exact fp32 rescore + gather/loss/emaw, 8 tokens per warp
    // =======================================================================
    __syncthreads();
    float* out_idx = out + OFF_IDX;

    for (int i = 0; i < 8; i++) {
        int lt = warp * 8 + i;
        int token = t0 + lt;
        const float* xr = x + (size_t)token * D;

        float4 xv[4];
#pragma unroll
        for (int c = 0; c < 4; c++)
            xv[c] = *(const float4*)&xr[lane * 4 + c * 128];

        int cnt = g_ccnt[token];
        float bestv = -3e38f;
        int   bk    = K;

        if (cnt <= CAP) {
            for (int j = 0; j < cnt; j++) {
                int k = g_cand[token * CAP + j];
                float s = 0.f;
#pragma unroll
                for (int c = 0; c < 4; c++) {
                    float4 wv = *(const float4*)&w[(size_t)k * D + lane * 4 + c * 128];
                    s += xv[c].x * wv.x + xv[c].y * wv.y + xv[c].z * wv.z + xv[c].w * wv.w;
                }
#pragma unroll
                for (int o = 16; o; o >>= 1) s += __shfl_xor_sync(0xffffffffu, s, o);
                s *= g_cbnorm[k];
                if (s > bestv || (s == bestv && k < bk)) { bestv = s; bk = k; }
            }
        } else {
            // overflow fallback: exact scan of all codes
            for (int k = 0; k < K; k++) {
                float s = 0.f;
#pragma unroll
                for (int c = 0; c < 4; c++) {
                    float4 wv = *(const float4*)&w[(size_t)k * D + lane * 4 + c * 128];
                    s += xv[c].x * wv.x + xv[c].y * wv.y + xv[c].z * wv.z + xv[c].w * wv.w;
                }
#pragma unroll
                for (int o = 16; o; o >>= 1) s += __shfl_xor_sync(0xffffffffu, s, o);
                s *= g_cbnorm[k];
                if (s > bestv || (s == bestv && k < bk)) { bestv = s; bk = k; }
            }
        }

        // gather + straight-through + loss + emaw scatter
        const float* wr = w + (size_t)bk * D;
        float* q    = out + OFF_Q + (size_t)token * D;
        float* emaw = out + OFF_EMAW + (size_t)bk * D;

        float lsum = 0.f;
#pragma unroll
        for (int c = 0; c < 4; c++) {
            int d = lane * 4 + c * 128;
            float4 wv = *(const float4*)&wr[d];
            float4 qv;
            qv.x = xv[c].x + (wv.x - xv[c].x);
            qv.y = xv[c].y + (wv.y - xv[c].y);
            qv.z = xv[c].z + (wv.z - xv[c].z);
            qv.w = xv[c].w + (wv.w - xv[c].w);
            *(float4*)&q[d] = qv;
            float d0 = wv.x - xv[c].x, d1 = wv.y - xv[c].y;
            float d2 = wv.z - xv[c].z, d3 = wv.w - xv[c].w;
            lsum += d0 * d0 + d1 * d1 + d2 * d2 + d3 * d3;
            atomicAdd(&emaw[d + 0], OMD * xv[c].x);
            atomicAdd(&emaw[d + 1], OMD * xv[c].y);
            atomicAdd(&emaw[d + 2], OMD * xv[c].z);
            atomicAdd(&emaw[d + 3], OMD * xv[c].w);
        }
#pragma unroll
        for (int o = 16; o; o >>= 1) lsum += __shfl_xor_sync(0xffffffffu, lsum, o);
        if (lane == 0) {
            atomicAdd(&g_loss, lsum);
            out_idx[token] = (float)bk;
            atomicAdd(&g_counts[bk], 1.0f);
        }
    }
}

// ---------------------------------------------------------------------------
// k4: cluster-size EMA pre-values + global sum
// ---------------------------------------------------------------------------
__global__ void __launch_bounds__(256) cs_kernel(const float* __restrict__ ecs) {
    __shared__ float red[256];
    int k = blockIdx.x * 256 + threadIdx.x;
    float v = ecs[k] * DECAYC + OMD * g_counts[k];
    g_cs_pre[k] = v;
    red[threadIdx.x] = v;
    __syncthreads();
    for (int s = 128; s; s >>= 1) {
        if (threadIdx.x < s) red[threadIdx.x] += red[threadIdx.x + s];
        __syncthreads();
    }
    if (threadIdx.x == 0) atomicAdd(&g_sum, red[0]);
}

// ---------------------------------------------------------------------------
// k5: finalize new_cs, new_weight, loss mean
// ---------------------------------------------------------------------------
__global__ void __launch_bounds__(256) finalize_kernel(float* __restrict__ out) {
    int gid = blockIdx.x * 256 + threadIdx.x;
    if (gid == 0) out[OFF_LOSS] = g_loss * (1.0f / ((float)N_TOK * (float)D));

    int k  = gid >> 7;
    int d4 = gid & 127;
    float n  = g_sum;
    float cs = (g_cs_pre[k] + EPSC) / (n + (float)K * EPSC) * n;
    if (d4 == 0) out[OFF_CS + k] = cs;

    size_t base = (size_t)k * D + d4 * 4;
#pragma unroll
    for (int q = 0; q < 4; q++) {
        float e = out[OFF_EMAW + base + q];
        out[OFF_W + base + q] = e / cs;
    }
}

// ---------------------------------------------------------------------------
extern "C" void kernel_launch(void* const* d_in, const int* in_sizes, int n_in,
                              void* d_out, int out_size) {
    const float* x    = (const float*)d_in[0];
    const float* w    = (const float*)d_in[1];
    const float* ecs  = (const float*)d_in[2];
    const float* emaw = (const float*)d_in[3];
    float* out = (float*)d_out;

    cudaFuncSetAttribute(mma_argmax_kernel,
                         cudaFuncAttributeMaxDynamicSharedMemorySize, SMEM_BYTES);

    setup_kernel<<<5120, 256>>>(w, emaw, out);
    mma_argmax_kernel<<<N_TOK / BLK_T, NTHREADS, SMEM_BYTES>>>(x, w, out);
    cs_kernel<<<K / 256, 256>>>(ecs);
    finalize_kernel<<<(K * D / 4) / 256, 256>>>(out);
}